// round 12
// baseline (speedup 1.0000x reference)
#include <cuda_runtime.h>
#include <cuda_bf16.h>
#include <cstdint>

#define NN 50000
#define NE 800000
#define DD 128

// ---------------- scratch (device globals; referenced ONLY in device code) ----
__device__ __align__(512) float g_s[(size_t)NN * DD];   // segment_sum(ef, dst)
__device__ float g_deg[NN];
__device__ float g_t2[(size_t)NN * DD];   // nf2 @ Wd2
__device__ float g_t3[(size_t)NN * DD];   // (S/deg)@M + 0.5 * t2
// bf16 hi/lo splits, B layout: B[n][k] = W[k][n]
__device__ __nv_bfloat16 g_Bn_h[DD * DD], g_Bn_l[DD * DD];     // W_node
__device__ __nv_bfloat16 g_Bd2_h[DD * DD], g_Bd2_l[DD * DD];   // dense_W[128:256]
__device__ __nv_bfloat16 g_Bm_h[DD * DD], g_Bm_l[DD * DD];     // M = We@Wd1

// ---------------- smem layout (32-bit words) ----------------------------------
#define WPAD 68
#define SA_H 0
#define SA_L (128 * WPAD)
#define SB_H (2 * 128 * WPAD)
#define SB_L (3 * 128 * WPAD)
#define STAGE (4 * 128 * WPAD)            // raw fp32 A staging (16384 words)
#define SMEM_BYTES (4 * 128 * WPAD * 4)   // 139264 (node passes)
#define SMEM_EO ((4 * 128 * WPAD + 128 * 128) * 4)  // 204800 (edge_out)
#define SCAT_SMEM 65536

// ---------------- helpers ------------------------------------------------------
__device__ __forceinline__ uint32_t smem_u32(const void* p) {
    uint32_t a;
    asm("{ .reg .u64 t; cvta.to.shared.u64 t, %1; cvt.u32.u64 %0, t; }" : "=r"(a) : "l"(p));
    return a;
}

__device__ __forceinline__ void split2(float x, float y, uint32_t& hi, uint32_t& lo) {
    __nv_bfloat162 h = __floats2bfloat162_rn(x, y);
    hi = *(uint32_t*)&h;
    float rx = x - __bfloat162float(__low2bfloat16(h));
    float ry = y - __bfloat162float(__high2bfloat16(h));
    __nv_bfloat162 l = __floats2bfloat162_rn(rx, ry);
    lo = *(uint32_t*)&l;
}

__device__ __forceinline__ void mma_bf16(float* d, const uint32_t* a,
                                         uint32_t b0, uint32_t b1) {
    asm volatile(
        "mma.sync.aligned.m16n8k16.row.col.f32.bf16.bf16.f32 "
        "{%0,%1,%2,%3}, {%4,%5,%6,%7}, {%8,%9}, {%0,%1,%2,%3};"
        : "+f"(d[0]), "+f"(d[1]), "+f"(d[2]), "+f"(d[3])
        : "r"(a[0]), "r"(a[1]), "r"(a[2]), "r"(a[3]), "r"(b0), "r"(b1));
}

// 512 threads fill the B tile pair
__device__ __forceinline__ void fillB(uint32_t* sm, const __nv_bfloat16* bh,
                                      const __nv_bfloat16* bl, int tid) {
#pragma unroll
    for (int i = 0; i < 16; i++) {
        int idx = tid + i * 512;
        int n = idx >> 6, w = idx & 63;
        sm[SB_H + n * WPAD + w] = *(const uint32_t*)(bh + (size_t)n * DD + 2 * w);
        sm[SB_L + n * WPAD + w] = *(const uint32_t*)(bl + (size_t)n * DD + 2 * w);
    }
}

// K=128 loop: warp computes 32 rows x 32 cols with 3-way bf16 split
__device__ __forceinline__ void kloop(const uint32_t* sm, int lane, int mbase,
                                      int nbase, float acc[2][4][4]) {
    const int g = lane >> 2, t = lane & 3;
#pragma unroll
    for (int ks = 0; ks < 8; ks++) {
        const int kw = ks * 8 + t;
        uint32_t ah[2][4], al[2][4];
#pragma unroll
        for (int mt = 0; mt < 2; mt++) {
            int r = mbase + mt * 16 + g;
            ah[mt][0] = sm[SA_H + r * WPAD + kw];
            ah[mt][1] = sm[SA_H + (r + 8) * WPAD + kw];
            ah[mt][2] = sm[SA_H + r * WPAD + kw + 4];
            ah[mt][3] = sm[SA_H + (r + 8) * WPAD + kw + 4];
            al[mt][0] = sm[SA_L + r * WPAD + kw];
            al[mt][1] = sm[SA_L + (r + 8) * WPAD + kw];
            al[mt][2] = sm[SA_L + r * WPAD + kw + 4];
            al[mt][3] = sm[SA_L + (r + 8) * WPAD + kw + 4];
        }
#pragma unroll
        for (int j = 0; j < 4; j++) {
            int n = nbase + j * 8 + g;
            uint32_t bh0 = sm[SB_H + n * WPAD + kw];
            uint32_t bh1 = sm[SB_H + n * WPAD + kw + 4];
            uint32_t bl0 = sm[SB_L + n * WPAD + kw];
            uint32_t bl1 = sm[SB_L + n * WPAD + kw + 4];
#pragma unroll
            for (int mt = 0; mt < 2; mt++) {
                mma_bf16(acc[mt][j], ah[mt], bh0, bh1);
                mma_bf16(acc[mt][j], ah[mt], bl0, bl1);
                mma_bf16(acc[mt][j], al[mt], bh0, bh1);
            }
        }
    }
}

__device__ __forceinline__ void zero_acc(float acc[2][4][4]) {
#pragma unroll
    for (int a = 0; a < 2; a++)
#pragma unroll
        for (int b = 0; b < 4; b++)
#pragma unroll
            for (int c = 0; c < 4; c++) acc[a][b][c] = 0.f;
}

// write warp's acc patch back into the smem A tile (bf16 hi/lo re-split)
__device__ __forceinline__ void acc_to_sa(uint32_t* sm, const float acc[2][4][4],
                                          int mbase, int nbase, int lane) {
    const int g = lane >> 2, t = lane & 3;
#pragma unroll
    for (int mt = 0; mt < 2; mt++) {
        int rA = mbase + mt * 16 + g, rB = rA + 8;
#pragma unroll
        for (int j = 0; j < 4; j++) {
            int w = (nbase >> 1) + j * 4 + t;
            uint32_t hi, lo;
            split2(acc[mt][j][0], acc[mt][j][1], hi, lo);
            sm[SA_H + rA * WPAD + w] = hi;
            sm[SA_L + rA * WPAD + w] = lo;
            split2(acc[mt][j][2], acc[mt][j][3], hi, lo);
            sm[SA_H + rB * WPAD + w] = hi;
            sm[SA_L + rB * WPAD + w] = lo;
        }
    }
}

// ---------------- prep kernels --------------------------------------------------
__global__ void zero_kernel() {
    int stride = gridDim.x * blockDim.x;
    int t = blockIdx.x * blockDim.x + threadIdx.x;
    for (int i = t; i < NN * DD; i += stride) g_s[i] = 0.0f;
    for (int i = t; i < NN; i += stride) g_deg[i] = 0.0f;
}

// one kernel: splits of W_node, dense_W[128:], and M=We@Wd1 (dot inline)
__global__ void prep_weights(const float* __restrict__ Wn,
                             const float* __restrict__ We,
                             const float* __restrict__ dW) {
    int idx = blockIdx.x * blockDim.x + threadIdx.x;
    if (idx >= DD * DD) return;
    int n = idx >> 7, k = idx & 127;

    float v = Wn[(size_t)k * DD + n];
    __nv_bfloat16 h = __float2bfloat16(v);
    g_Bn_h[idx] = h;
    g_Bn_l[idx] = __float2bfloat16(v - __bfloat162float(h));

    v = dW[(size_t)(128 + k) * DD + n];
    h = __float2bfloat16(v);
    g_Bd2_h[idx] = h;
    g_Bd2_l[idx] = __float2bfloat16(v - __bfloat162float(h));

    float m = 0.f;
#pragma unroll 4
    for (int j = 0; j < DD; j++)
        m = fmaf(We[(size_t)k * DD + j], dW[(size_t)j * DD + n], m);
    h = __float2bfloat16(m);
    g_Bm_h[idx] = h;
    g_Bm_l[idx] = __float2bfloat16(m - __bfloat162float(h));
}

// scatter 128 contiguous ef rows via smem + TMA bulk reductions
__global__ __launch_bounds__(256)
void scatter_ef(const float* __restrict__ ef, const int* __restrict__ dst) {
    extern __shared__ __align__(16) float buf[];   // 128 rows x 128 f32 = 64KB
    const int tid = threadIdx.x;
    const int e0 = blockIdx.x * 128;
    const float4* src = (const float4*)(ef + (size_t)e0 * DD);
    float4* b4 = (float4*)buf;
#pragma unroll
    for (int i = 0; i < 16; i++)
        b4[tid + i * 256] = src[tid + i * 256];
    __syncthreads();
    asm volatile("fence.proxy.async.shared::cta;" ::: "memory");
    if (tid < 128) {
        int e = e0 + tid;
        int dn = dst[e];
        uint32_t sptr = smem_u32(buf + tid * DD);
        float* gptr = g_s + (size_t)dn * DD;
        asm volatile(
            "cp.reduce.async.bulk.global.shared::cta.bulk_group.add.f32 [%0], [%1], 512;"
            :: "l"(gptr), "r"(sptr) : "memory");
        asm volatile("red.global.add.f32 [%0], %1;"
                     :: "l"(g_deg + dn), "f"(1.0f) : "memory");
    }
    asm volatile("cp.async.bulk.commit_group;" ::: "memory");
    asm volatile("cp.async.bulk.wait_group 0;" ::: "memory");
}

// ---------------- fused node pass A: nf2 = relu(nf@Wn + b); t2 = nf2@Wd2 -------
__global__ __launch_bounds__(512, 1)
void node_pass_a(const float* __restrict__ nf, const float* __restrict__ bias,
                 float* __restrict__ nf2out) {
    extern __shared__ uint32_t sm[];
    const int tid = threadIdx.x, lane = tid & 31, wid = tid >> 5;
    const int rowbase = blockIdx.x * 128;
    const int mbase = (wid & 3) * 32, nbase = (wid >> 2) * 32;
    const int g = lane >> 2, t = lane & 3;

    fillB(sm, g_Bn_h, g_Bn_l, tid);
#pragma unroll
    for (int i = 0; i < 16; i++) {
        int idx = tid + i * 512;
        int r = idx >> 6, w = idx & 63;
        int row = rowbase + r;
        float2 v = make_float2(0.f, 0.f);
        if (row < NN) v = *(const float2*)(nf + (size_t)row * DD + 2 * w);
        split2(v.x, v.y, sm[SA_H + r * WPAD + w], sm[SA_L + r * WPAD + w]);
    }
    __syncthreads();

    float acc[2][4][4];
    zero_acc(acc);
    kloop(sm, lane, mbase, nbase, acc);
    __syncthreads();

    // epilogue 1: bias + relu -> nf2 (global) and re-split into SA
#pragma unroll
    for (int mt = 0; mt < 2; mt++) {
        int rowA = rowbase + mbase + mt * 16 + g;
#pragma unroll
        for (int j = 0; j < 4; j++) {
            int c = nbase + j * 8 + 2 * t;
            float2 bv = *(const float2*)(bias + c);
            acc[mt][j][0] = fmaxf(acc[mt][j][0] + bv.x, 0.f);
            acc[mt][j][1] = fmaxf(acc[mt][j][1] + bv.y, 0.f);
            acc[mt][j][2] = fmaxf(acc[mt][j][2] + bv.x, 0.f);
            acc[mt][j][3] = fmaxf(acc[mt][j][3] + bv.y, 0.f);
            if (rowA < NN)
                *(float2*)(nf2out + (size_t)rowA * DD + c) =
                    make_float2(acc[mt][j][0], acc[mt][j][1]);
            if (rowA + 8 < NN)
                *(float2*)(nf2out + (size_t)(rowA + 8) * DD + c) =
                    make_float2(acc[mt][j][2], acc[mt][j][3]);
        }
    }
    acc_to_sa(sm, acc, mbase, nbase, lane);
    fillB(sm, g_Bd2_h, g_Bd2_l, tid);
    __syncthreads();

    zero_acc(acc);
    kloop(sm, lane, mbase, nbase, acc);

#pragma unroll
    for (int mt = 0; mt < 2; mt++) {
        int rowA = rowbase + mbase + mt * 16 + g;
#pragma unroll
        for (int j = 0; j < 4; j++) {
            int c = nbase + j * 8 + 2 * t;
            if (rowA < NN)
                *(float2*)(g_t2 + (size_t)rowA * DD + c) =
                    make_float2(acc[mt][j][0], acc[mt][j][1]);
            if (rowA + 8 < NN)
                *(float2*)(g_t2 + (size_t)(rowA + 8) * DD + c) =
                    make_float2(acc[mt][j][2], acc[mt][j][3]);
        }
    }
}

// ---------------- node pass B: t3 = (S/deg) @ M + 0.5*t2 ------------------------
__global__ __launch_bounds__(512, 1)
void node_pass_b() {
    extern __shared__ uint32_t sm[];
    const int tid = threadIdx.x, lane = tid & 31, wid = tid >> 5;
    const int rowbase = blockIdx.x * 128;
    const int mbase = (wid & 3) * 32, nbase = (wid >> 2) * 32;
    const int g = lane >> 2, t = lane & 3;

    fillB(sm, g_Bm_h, g_Bm_l, tid);
#pragma unroll
    for (int i = 0; i < 16; i++) {
        int idx = tid + i * 512;
        int r = idx >> 6, w = idx & 63;
        int row = rowbase + r;
        float2 v = make_float2(0.f, 0.f);
        if (row < NN) {
            float s = 1.f / fmaxf(g_deg[row], 1.f);
            v = *(const float2*)(g_s + (size_t)row * DD + 2 * w);
            v.x *= s; v.y *= s;
        }
        split2(v.x, v.y, sm[SA_H + r * WPAD + w], sm[SA_L + r * WPAD + w]);
    }
    __syncthreads();

    float acc[2][4][4];
    zero_acc(acc);
    kloop(sm, lane, mbase, nbase, acc);

#pragma unroll
    for (int mt = 0; mt < 2; mt++) {
        int rowA = rowbase + mbase + mt * 16 + g;
#pragma unroll
        for (int j = 0; j < 4; j++) {
            int c = nbase + j * 8 + 2 * t;
            if (rowA < NN) {
                float2 u = *(const float2*)(g_t2 + (size_t)rowA * DD + c);
                *(float2*)(g_t3 + (size_t)rowA * DD + c) =
                    make_float2(acc[mt][j][0] + 0.5f * u.x,
                                acc[mt][j][1] + 0.5f * u.y);
            }
            if (rowA + 8 < NN) {
                float2 u = *(const float2*)(g_t2 + (size_t)(rowA + 8) * DD + c);
                *(float2*)(g_t3 + (size_t)(rowA + 8) * DD + c) =
                    make_float2(acc[mt][j][2] + 0.5f * u.x,
                                acc[mt][j][3] + 0.5f * u.y);
            }
        }
    }
}

// ---------------- persistent fused edge output kernel ---------------------------
// ef2 = relu(ef @ M + t3[dst] + 0.5*t2[src] + db + eb)
// B resident per CTA; A double-buffered: raw fp32 tile staged via cp.async.
__global__ __launch_bounds__(512, 1)
void edge_out_gemm(const float* __restrict__ ef, const int* __restrict__ src,
                   const int* __restrict__ dst, const float* __restrict__ db,
                   const float* __restrict__ eb, float* __restrict__ out) {
    extern __shared__ uint32_t sm[];
    float* stage = (float*)(sm + STAGE);
    const int tid = threadIdx.x, lane = tid & 31, wid = tid >> 5;
    const int mbase = (wid & 3) * 32, nbase = (wid >> 2) * 32;
    const int g = lane >> 2, t = lane & 3;
    const int NT = NE / 128;

    fillB(sm, g_Bm_h, g_Bm_l, tid);

    // prefetch first tile into staging
    int tile = blockIdx.x;
    {
        const char* gsrc = (const char*)(ef + (size_t)tile * 128 * DD);
        uint32_t sdst = smem_u32(stage);
#pragma unroll
        for (int i = 0; i < 8; i++) {
            uint32_t d = sdst + (tid + i * 512) * 16;
            const char* s = gsrc + (size_t)(tid + i * 512) * 16;
            asm volatile("cp.async.cg.shared.global [%0], [%1], 16;"
                         :: "r"(d), "l"(s) : "memory");
        }
        asm volatile("cp.async.commit_group;" ::: "memory");
    }

    for (; tile < NT; tile += gridDim.x) {
        asm volatile("cp.async.wait_group 0;" ::: "memory");
        __syncthreads();

        // split staging -> SA
#pragma unroll
        for (int i = 0; i < 16; i++) {
            int idx = tid + i * 512;
            int r = idx >> 6, w = idx & 63;
            float2 v = *(const float2*)(stage + r * DD + 2 * w);
            split2(v.x, v.y, sm[SA_H + r * WPAD + w], sm[SA_L + r * WPAD + w]);
        }
        __syncthreads();   // SA ready AND staging fully consumed

        // prefetch next tile into staging (overlaps kloop)
        int ntile = tile + gridDim.x;
        if (ntile < NT) {
            const char* gsrc = (const char*)(ef + (size_t)ntile * 128 * DD);
            uint32_t sdst = smem_u32(stage);
#pragma unroll
            for (int i = 0; i < 8; i++) {
                uint32_t d = sdst + (tid + i * 512) * 16;
                const char* s = gsrc + (size_t)(tid + i * 512) * 16;
                asm volatile("cp.async.cg.shared.global [%0], [%1], 16;"
                             :: "r"(d), "l"(s) : "memory");
            }
        }
        asm volatile("cp.async.commit_group;" ::: "memory");

        float acc[2][4][4];
        zero_acc(acc);
        kloop(sm, lane, mbase, nbase, acc);

        const int e0 = tile * 128;
#pragma unroll
        for (int mt = 0; mt < 2; mt++) {
            int e = e0 + mbase + mt * 16 + g;
            int dnA = dst[e], snA = src[e];
            int dnB = dst[e + 8], snB = src[e + 8];
            const float* t3A = g_t3 + (size_t)dnA * DD;
            const float* t2A = g_t2 + (size_t)snA * DD;
            const float* t3B = g_t3 + (size_t)dnB * DD;
            const float* t2B = g_t2 + (size_t)snB * DD;
#pragma unroll
            for (int j = 0; j < 4; j++) {
                int c = nbase + j * 8 + 2 * t;
                float2 d1 = *(const float2*)(db + c);
                float2 d2 = *(const float2*)(eb + c);
                float bx = d1.x + d2.x, by = d1.y + d2.y;

                float2 p1 = *(const float2*)(t3A + c);
                float2 p2 = *(const float2*)(t2A + c);
                float2 oA;
                oA.x = fmaxf(acc[mt][j][0] + p1.x + 0.5f * p2.x + bx, 0.f);
                oA.y = fmaxf(acc[mt][j][1] + p1.y + 0.5f * p2.y + by, 0.f);
                *(float2*)(out + (size_t)e * DD + c) = oA;

                float2 q1 = *(const float2*)(t3B + c);
                float2 q2 = *(const float2*)(t2B + c);
                float2 oB;
                oB.x = fmaxf(acc[mt][j][2] + q1.x + 0.5f * q2.x + bx, 0.f);
                oB.y = fmaxf(acc[mt][j][3] + q1.y + 0.5f * q2.y + by, 0.f);
                *(float2*)(out + (size_t)(e + 8) * DD + c) = oB;
            }
        }
        __syncthreads();   // all warps done reading SA before next split
    }
}

// ---------------- launch ------------------------------------------------------
extern "C" void kernel_launch(void* const* d_in, const int* in_sizes, int n_in,
                              void* d_out, int out_size) {
    (void)in_sizes; (void)n_in; (void)out_size;
    const float* nf        = (const float*)d_in[0];
    const float* ef        = (const float*)d_in[1];
    const float* W_node    = (const float*)d_in[2];
    const float* W_edge    = (const float*)d_in[3];
    const float* node_bias = (const float*)d_in[4];
    const float* edge_bias = (const float*)d_in[5];
    const float* dense_W   = (const float*)d_in[6];
    const float* dense_b   = (const float*)d_in[7];
    const int*   src       = (const int*)d_in[8];
    const int*   dst       = (const int*)d_in[9];

    float* nf2 = (float*)d_out;
    float* ef2 = (float*)d_out + (size_t)NN * DD;

    static cudaStream_t s2 = nullptr;
    static cudaEvent_t ev1 = nullptr, ev2 = nullptr;
    if (!s2) {
        cudaStreamCreateWithFlags(&s2, cudaStreamNonBlocking);
        cudaEventCreateWithFlags(&ev1, cudaEventDisableTiming);
        cudaEventCreateWithFlags(&ev2, cudaEventDisableTiming);
    }

    cudaFuncSetAttribute(scatter_ef, cudaFuncAttributeMaxDynamicSharedMemorySize, SCAT_SMEM);
    cudaFuncSetAttribute(node_pass_a, cudaFuncAttributeMaxDynamicSharedMemorySize, SMEM_BYTES);
    cudaFuncSetAttribute(node_pass_b, cudaFuncAttributeMaxDynamicSharedMemorySize, SMEM_BYTES);
    cudaFuncSetAttribute(edge_out_gemm, cudaFuncAttributeMaxDynamicSharedMemorySize, SMEM_EO);

    const int NBLK = (NN + 127) / 128;

    zero_kernel<<<1024, 256>>>();
    prep_weights<<<64, 256>>>(W_node, W_edge, dense_W);

    // fork: scatter on s2 (after zero/prep), node_pass_a on main — independent
    cudaEventRecord(ev1, 0);
    cudaStreamWaitEvent(s2, ev1, 0);
    scatter_ef<<<NE / 128, 256, SCAT_SMEM, s2>>>(ef, dst);
    cudaEventRecord(ev2, s2);

    node_pass_a<<<NBLK, 512, SMEM_BYTES>>>(nf, node_bias, nf2);

    cudaStreamWaitEvent(0, ev2, 0);   // join
    node_pass_b<<<NBLK, 512, SMEM_BYTES>>>();
    edge_out_gemm<<<148, 512, SMEM_EO>>>(ef, src, dst, dense_b, edge_bias, ef2);
}

// round 13
// speedup vs baseline: 1.0091x; 1.0091x over previous
#include <cuda_runtime.h>
#include <cuda_bf16.h>
#include <cstdint>

#define NN 50000
#define NE 800000
#define DD 128

// ---------------- scratch (device globals; referenced ONLY in device code) ----
__device__ __align__(512) float g_s[(size_t)NN * DD];   // segment_sum(ef, dst)
__device__ float g_deg[NN];
__device__ float g_t2[(size_t)NN * DD];   // nf2 @ Wd2
__device__ float g_t3[(size_t)NN * DD];   // (S/deg)@M + 0.5 * t2
// bf16 hi/lo splits, B layout: B[n][k] = W[k][n]
__device__ __nv_bfloat16 g_Bn_h[DD * DD], g_Bn_l[DD * DD];     // W_node
__device__ __nv_bfloat16 g_Bd2_h[DD * DD], g_Bd2_l[DD * DD];   // dense_W[128:256]
__device__ __nv_bfloat16 g_Bm_h[DD * DD], g_Bm_l[DD * DD];     // M = We@Wd1

// ---------------- smem layout (32-bit words) ----------------------------------
#define WPAD 68
// node passes (128-row A), 512 threads
#define SA_H 0
#define SA_L (128 * WPAD)
#define SB_H (2 * 128 * WPAD)
#define SB_L (3 * 128 * WPAD)
#define SMEM_BYTES (4 * 128 * WPAD * 4)   // 139264
// edge_out (64-row A), 256 threads, 2 CTAs/SM
#define EA_H 0
#define EA_L (64 * WPAD)
#define EB_H (128 * WPAD)
#define EB_L (256 * WPAD)
#define SMEM_EO (384 * WPAD * 4)          // 104448
#define SCAT_SMEM 65536

// ---------------- helpers ------------------------------------------------------
__device__ __forceinline__ uint32_t smem_u32(const void* p) {
    uint32_t a;
    asm("{ .reg .u64 t; cvta.to.shared.u64 t, %1; cvt.u32.u64 %0, t; }" : "=r"(a) : "l"(p));
    return a;
}

__device__ __forceinline__ void split2(float x, float y, uint32_t& hi, uint32_t& lo) {
    __nv_bfloat162 h = __floats2bfloat162_rn(x, y);
    hi = *(uint32_t*)&h;
    float rx = x - __bfloat162float(__low2bfloat16(h));
    float ry = y - __bfloat162float(__high2bfloat16(h));
    __nv_bfloat162 l = __floats2bfloat162_rn(rx, ry);
    lo = *(uint32_t*)&l;
}

__device__ __forceinline__ void mma_bf16(float* d, const uint32_t* a,
                                         uint32_t b0, uint32_t b1) {
    asm volatile(
        "mma.sync.aligned.m16n8k16.row.col.f32.bf16.bf16.f32 "
        "{%0,%1,%2,%3}, {%4,%5,%6,%7}, {%8,%9}, {%0,%1,%2,%3};"
        : "+f"(d[0]), "+f"(d[1]), "+f"(d[2]), "+f"(d[3])
        : "r"(a[0]), "r"(a[1]), "r"(a[2]), "r"(a[3]), "r"(b0), "r"(b1));
}

// 512 threads fill the node B tile pair
__device__ __forceinline__ void fillB(uint32_t* sm, const __nv_bfloat16* bh,
                                      const __nv_bfloat16* bl, int tid) {
#pragma unroll
    for (int i = 0; i < 16; i++) {
        int idx = tid + i * 512;
        int n = idx >> 6, w = idx & 63;
        sm[SB_H + n * WPAD + w] = *(const uint32_t*)(bh + (size_t)n * DD + 2 * w);
        sm[SB_L + n * WPAD + w] = *(const uint32_t*)(bl + (size_t)n * DD + 2 * w);
    }
}

// 256 threads fill the edge B tile pair
__device__ __forceinline__ void fillB_eo(uint32_t* sm, const __nv_bfloat16* bh,
                                         const __nv_bfloat16* bl, int tid) {
#pragma unroll
    for (int i = 0; i < 32; i++) {
        int idx = tid + i * 256;
        int n = idx >> 6, w = idx & 63;
        sm[EB_H + n * WPAD + w] = *(const uint32_t*)(bh + (size_t)n * DD + 2 * w);
        sm[EB_L + n * WPAD + w] = *(const uint32_t*)(bl + (size_t)n * DD + 2 * w);
    }
}

// K=128 loop (node): warp computes 32 rows x 32 cols with 3-way bf16 split
__device__ __forceinline__ void kloop(const uint32_t* sm, int lane, int mbase,
                                      int nbase, float acc[2][4][4]) {
    const int g = lane >> 2, t = lane & 3;
#pragma unroll
    for (int ks = 0; ks < 8; ks++) {
        const int kw = ks * 8 + t;
        uint32_t ah[2][4], al[2][4];
#pragma unroll
        for (int mt = 0; mt < 2; mt++) {
            int r = mbase + mt * 16 + g;
            ah[mt][0] = sm[SA_H + r * WPAD + kw];
            ah[mt][1] = sm[SA_H + (r + 8) * WPAD + kw];
            ah[mt][2] = sm[SA_H + r * WPAD + kw + 4];
            ah[mt][3] = sm[SA_H + (r + 8) * WPAD + kw + 4];
            al[mt][0] = sm[SA_L + r * WPAD + kw];
            al[mt][1] = sm[SA_L + (r + 8) * WPAD + kw];
            al[mt][2] = sm[SA_L + r * WPAD + kw + 4];
            al[mt][3] = sm[SA_L + (r + 8) * WPAD + kw + 4];
        }
#pragma unroll
        for (int j = 0; j < 4; j++) {
            int n = nbase + j * 8 + g;
            uint32_t bh0 = sm[SB_H + n * WPAD + kw];
            uint32_t bh1 = sm[SB_H + n * WPAD + kw + 4];
            uint32_t bl0 = sm[SB_L + n * WPAD + kw];
            uint32_t bl1 = sm[SB_L + n * WPAD + kw + 4];
#pragma unroll
            for (int mt = 0; mt < 2; mt++) {
                mma_bf16(acc[mt][j], ah[mt], bh0, bh1);
                mma_bf16(acc[mt][j], ah[mt], bl0, bl1);
                mma_bf16(acc[mt][j], al[mt], bh0, bh1);
            }
        }
    }
}

// K=128 loop (edge): same math, EA/EB offsets
__device__ __forceinline__ void kloop_eo(const uint32_t* sm, int lane, int mbase,
                                         int nbase, float acc[2][4][4]) {
    const int g = lane >> 2, t = lane & 3;
#pragma unroll
    for (int ks = 0; ks < 8; ks++) {
        const int kw = ks * 8 + t;
        uint32_t ah[2][4], al[2][4];
#pragma unroll
        for (int mt = 0; mt < 2; mt++) {
            int r = mbase + mt * 16 + g;
            ah[mt][0] = sm[EA_H + r * WPAD + kw];
            ah[mt][1] = sm[EA_H + (r + 8) * WPAD + kw];
            ah[mt][2] = sm[EA_H + r * WPAD + kw + 4];
            ah[mt][3] = sm[EA_H + (r + 8) * WPAD + kw + 4];
            al[mt][0] = sm[EA_L + r * WPAD + kw];
            al[mt][1] = sm[EA_L + (r + 8) * WPAD + kw];
            al[mt][2] = sm[EA_L + r * WPAD + kw + 4];
            al[mt][3] = sm[EA_L + (r + 8) * WPAD + kw + 4];
        }
#pragma unroll
        for (int j = 0; j < 4; j++) {
            int n = nbase + j * 8 + g;
            uint32_t bh0 = sm[EB_H + n * WPAD + kw];
            uint32_t bh1 = sm[EB_H + n * WPAD + kw + 4];
            uint32_t bl0 = sm[EB_L + n * WPAD + kw];
            uint32_t bl1 = sm[EB_L + n * WPAD + kw + 4];
#pragma unroll
            for (int mt = 0; mt < 2; mt++) {
                mma_bf16(acc[mt][j], ah[mt], bh0, bh1);
                mma_bf16(acc[mt][j], ah[mt], bl0, bl1);
                mma_bf16(acc[mt][j], al[mt], bh0, bh1);
            }
        }
    }
}

__device__ __forceinline__ void zero_acc(float acc[2][4][4]) {
#pragma unroll
    for (int a = 0; a < 2; a++)
#pragma unroll
        for (int b = 0; b < 4; b++)
#pragma unroll
            for (int c = 0; c < 4; c++) acc[a][b][c] = 0.f;
}

// write warp's acc patch back into the node smem A tile (bf16 hi/lo re-split)
__device__ __forceinline__ void acc_to_sa(uint32_t* sm, const float acc[2][4][4],
                                          int mbase, int nbase, int lane) {
    const int g = lane >> 2, t = lane & 3;
#pragma unroll
    for (int mt = 0; mt < 2; mt++) {
        int rA = mbase + mt * 16 + g, rB = rA + 8;
#pragma unroll
        for (int j = 0; j < 4; j++) {
            int w = (nbase >> 1) + j * 4 + t;
            uint32_t hi, lo;
            split2(acc[mt][j][0], acc[mt][j][1], hi, lo);
            sm[SA_H + rA * WPAD + w] = hi;
            sm[SA_L + rA * WPAD + w] = lo;
            split2(acc[mt][j][2], acc[mt][j][3], hi, lo);
            sm[SA_H + rB * WPAD + w] = hi;
            sm[SA_L + rB * WPAD + w] = lo;
        }
    }
}

// ---------------- prep kernels --------------------------------------------------
__global__ void zero_kernel() {
    int stride = gridDim.x * blockDim.x;
    int t = blockIdx.x * blockDim.x + threadIdx.x;
    for (int i = t; i < NN * DD; i += stride) g_s[i] = 0.0f;
    for (int i = t; i < NN; i += stride) g_deg[i] = 0.0f;
}

// one kernel: splits of W_node, dense_W[128:], and M=We@Wd1 (dot inline)
__global__ void prep_weights(const float* __restrict__ Wn,
                             const float* __restrict__ We,
                             const float* __restrict__ dW) {
    int idx = blockIdx.x * blockDim.x + threadIdx.x;
    if (idx >= DD * DD) return;
    int n = idx >> 7, k = idx & 127;

    float v = Wn[(size_t)k * DD + n];
    __nv_bfloat16 h = __float2bfloat16(v);
    g_Bn_h[idx] = h;
    g_Bn_l[idx] = __float2bfloat16(v - __bfloat162float(h));

    v = dW[(size_t)(128 + k) * DD + n];
    h = __float2bfloat16(v);
    g_Bd2_h[idx] = h;
    g_Bd2_l[idx] = __float2bfloat16(v - __bfloat162float(h));

    float m = 0.f;
#pragma unroll 4
    for (int j = 0; j < DD; j++)
        m = fmaf(We[(size_t)k * DD + j], dW[(size_t)j * DD + n], m);
    h = __float2bfloat16(m);
    g_Bm_h[idx] = h;
    g_Bm_l[idx] = __float2bfloat16(m - __bfloat162float(h));
}

// scatter 128 contiguous ef rows via smem + TMA bulk reductions
__global__ __launch_bounds__(256)
void scatter_ef(const float* __restrict__ ef, const int* __restrict__ dst) {
    extern __shared__ __align__(16) float buf[];   // 128 rows x 128 f32 = 64KB
    const int tid = threadIdx.x;
    const int e0 = blockIdx.x * 128;
    const float4* src = (const float4*)(ef + (size_t)e0 * DD);
    float4* b4 = (float4*)buf;
#pragma unroll
    for (int i = 0; i < 16; i++)
        b4[tid + i * 256] = src[tid + i * 256];
    __syncthreads();
    asm volatile("fence.proxy.async.shared::cta;" ::: "memory");
    if (tid < 128) {
        int e = e0 + tid;
        int dn = dst[e];
        uint32_t sptr = smem_u32(buf + tid * DD);
        float* gptr = g_s + (size_t)dn * DD;
        asm volatile(
            "cp.reduce.async.bulk.global.shared::cta.bulk_group.add.f32 [%0], [%1], 512;"
            :: "l"(gptr), "r"(sptr) : "memory");
        asm volatile("red.global.add.f32 [%0], %1;"
                     :: "l"(g_deg + dn), "f"(1.0f) : "memory");
    }
    asm volatile("cp.async.bulk.commit_group;" ::: "memory");
    asm volatile("cp.async.bulk.wait_group 0;" ::: "memory");
}

// ---------------- fused node pass A: nf2 = relu(nf@Wn + b); t2 = nf2@Wd2 -------
__global__ __launch_bounds__(512, 1)
void node_pass_a(const float* __restrict__ nf, const float* __restrict__ bias,
                 float* __restrict__ nf2out) {
    extern __shared__ uint32_t sm[];
    const int tid = threadIdx.x, lane = tid & 31, wid = tid >> 5;
    const int rowbase = blockIdx.x * 128;
    const int mbase = (wid & 3) * 32, nbase = (wid >> 2) * 32;
    const int g = lane >> 2, t = lane & 3;

    fillB(sm, g_Bn_h, g_Bn_l, tid);
#pragma unroll
    for (int i = 0; i < 16; i++) {
        int idx = tid + i * 512;
        int r = idx >> 6, w = idx & 63;
        int row = rowbase + r;
        float2 v = make_float2(0.f, 0.f);
        if (row < NN) v = *(const float2*)(nf + (size_t)row * DD + 2 * w);
        split2(v.x, v.y, sm[SA_H + r * WPAD + w], sm[SA_L + r * WPAD + w]);
    }
    __syncthreads();

    float acc[2][4][4];
    zero_acc(acc);
    kloop(sm, lane, mbase, nbase, acc);
    __syncthreads();

    // epilogue 1: bias + relu -> nf2 (global) and re-split into SA
#pragma unroll
    for (int mt = 0; mt < 2; mt++) {
        int rowA = rowbase + mbase + mt * 16 + g;
#pragma unroll
        for (int j = 0; j < 4; j++) {
            int c = nbase + j * 8 + 2 * t;
            float2 bv = *(const float2*)(bias + c);
            acc[mt][j][0] = fmaxf(acc[mt][j][0] + bv.x, 0.f);
            acc[mt][j][1] = fmaxf(acc[mt][j][1] + bv.y, 0.f);
            acc[mt][j][2] = fmaxf(acc[mt][j][2] + bv.x, 0.f);
            acc[mt][j][3] = fmaxf(acc[mt][j][3] + bv.y, 0.f);
            if (rowA < NN)
                *(float2*)(nf2out + (size_t)rowA * DD + c) =
                    make_float2(acc[mt][j][0], acc[mt][j][1]);
            if (rowA + 8 < NN)
                *(float2*)(nf2out + (size_t)(rowA + 8) * DD + c) =
                    make_float2(acc[mt][j][2], acc[mt][j][3]);
        }
    }
    acc_to_sa(sm, acc, mbase, nbase, lane);
    fillB(sm, g_Bd2_h, g_Bd2_l, tid);
    __syncthreads();

    zero_acc(acc);
    kloop(sm, lane, mbase, nbase, acc);

#pragma unroll
    for (int mt = 0; mt < 2; mt++) {
        int rowA = rowbase + mbase + mt * 16 + g;
#pragma unroll
        for (int j = 0; j < 4; j++) {
            int c = nbase + j * 8 + 2 * t;
            if (rowA < NN)
                *(float2*)(g_t2 + (size_t)rowA * DD + c) =
                    make_float2(acc[mt][j][0], acc[mt][j][1]);
            if (rowA + 8 < NN)
                *(float2*)(g_t2 + (size_t)(rowA + 8) * DD + c) =
                    make_float2(acc[mt][j][2], acc[mt][j][3]);
        }
    }
}

// ---------------- node pass B: t3 = (S/deg) @ M + 0.5*t2 ------------------------
__global__ __launch_bounds__(512, 1)
void node_pass_b() {
    extern __shared__ uint32_t sm[];
    const int tid = threadIdx.x, lane = tid & 31, wid = tid >> 5;
    const int rowbase = blockIdx.x * 128;
    const int mbase = (wid & 3) * 32, nbase = (wid >> 2) * 32;
    const int g = lane >> 2, t = lane & 3;

    fillB(sm, g_Bm_h, g_Bm_l, tid);
#pragma unroll
    for (int i = 0; i < 16; i++) {
        int idx = tid + i * 512;
        int r = idx >> 6, w = idx & 63;
        int row = rowbase + r;
        float2 v = make_float2(0.f, 0.f);
        if (row < NN) {
            float s = 1.f / fmaxf(g_deg[row], 1.f);
            v = *(const float2*)(g_s + (size_t)row * DD + 2 * w);
            v.x *= s; v.y *= s;
        }
        split2(v.x, v.y, sm[SA_H + r * WPAD + w], sm[SA_L + r * WPAD + w]);
    }
    __syncthreads();

    float acc[2][4][4];
    zero_acc(acc);
    kloop(sm, lane, mbase, nbase, acc);

#pragma unroll
    for (int mt = 0; mt < 2; mt++) {
        int rowA = rowbase + mbase + mt * 16 + g;
#pragma unroll
        for (int j = 0; j < 4; j++) {
            int c = nbase + j * 8 + 2 * t;
            if (rowA < NN) {
                float2 u = *(const float2*)(g_t2 + (size_t)rowA * DD + c);
                *(float2*)(g_t3 + (size_t)rowA * DD + c) =
                    make_float2(acc[mt][j][0] + 0.5f * u.x,
                                acc[mt][j][1] + 0.5f * u.y);
            }
            if (rowA + 8 < NN) {
                float2 u = *(const float2*)(g_t2 + (size_t)(rowA + 8) * DD + c);
                *(float2*)(g_t3 + (size_t)(rowA + 8) * DD + c) =
                    make_float2(acc[mt][j][2] + 0.5f * u.x,
                                acc[mt][j][3] + 0.5f * u.y);
            }
        }
    }
}

// ---------------- fused edge output kernel (64-edge tiles, 2 CTAs/SM) -----------
// ef2 = relu(ef @ M + t3[dst] + 0.5*t2[src] + db + eb)
__global__ __launch_bounds__(256, 2)
void edge_out_gemm(const float* __restrict__ ef, const int* __restrict__ src,
                   const int* __restrict__ dst, const float* __restrict__ db,
                   const float* __restrict__ eb, float* __restrict__ out) {
    extern __shared__ uint32_t sm[];
    const int tid = threadIdx.x, lane = tid & 31, wid = tid >> 5;
    const int e0 = blockIdx.x * 64;
    const int mbase = (wid & 1) * 32, nbase = (wid >> 1) * 32;
    const int g = lane >> 2, t = lane & 3;

    fillB_eo(sm, g_Bm_h, g_Bm_l, tid);
#pragma unroll
    for (int i = 0; i < 16; i++) {
        int idx = tid + i * 256;
        int r = idx >> 6, w = idx & 63;
        float2 v = *(const float2*)(ef + (size_t)(e0 + r) * DD + 2 * w);
        split2(v.x, v.y, sm[EA_H + r * WPAD + w], sm[EA_L + r * WPAD + w]);
    }
    __syncthreads();

    float acc[2][4][4];
    zero_acc(acc);
    kloop_eo(sm, lane, mbase, nbase, acc);

#pragma unroll
    for (int mt = 0; mt < 2; mt++) {
        int e = e0 + mbase + mt * 16 + g;
        int dnA = dst[e], snA = src[e];
        int dnB = dst[e + 8], snB = src[e + 8];
        const float* t3A = g_t3 + (size_t)dnA * DD;
        const float* t2A = g_t2 + (size_t)snA * DD;
        const float* t3B = g_t3 + (size_t)dnB * DD;
        const float* t2B = g_t2 + (size_t)snB * DD;
#pragma unroll
        for (int j = 0; j < 4; j++) {
            int c = nbase + j * 8 + 2 * t;
            float2 d1 = *(const float2*)(db + c);
            float2 d2 = *(const float2*)(eb + c);
            float bx = d1.x + d2.x, by = d1.y + d2.y;

            float2 p1 = *(const float2*)(t3A + c);
            float2 p2 = *(const float2*)(t2A + c);
            float2 oA;
            oA.x = fmaxf(acc[mt][j][0] + p1.x + 0.5f * p2.x + bx, 0.f);
            oA.y = fmaxf(acc[mt][j][1] + p1.y + 0.5f * p2.y + by, 0.f);
            *(float2*)(out + (size_t)e * DD + c) = oA;

            float2 q1 = *(const float2*)(t3B + c);
            float2 q2 = *(const float2*)(t2B + c);
            float2 oB;
            oB.x = fmaxf(acc[mt][j][2] + q1.x + 0.5f * q2.x + bx, 0.f);
            oB.y = fmaxf(acc[mt][j][3] + q1.y + 0.5f * q2.y + by, 0.f);
            *(float2*)(out + (size_t)(e + 8) * DD + c) = oB;
        }
    }
}

// ---------------- launch ------------------------------------------------------
extern "C" void kernel_launch(void* const* d_in, const int* in_sizes, int n_in,
                              void* d_out, int out_size) {
    (void)in_sizes; (void)n_in; (void)out_size;
    const float* nf        = (const float*)d_in[0];
    const float* ef        = (const float*)d_in[1];
    const float* W_node    = (const float*)d_in[2];
    const float* W_edge    = (const float*)d_in[3];
    const float* node_bias = (const float*)d_in[4];
    const float* edge_bias = (const float*)d_in[5];
    const float* dense_W   = (const float*)d_in[6];
    const float* dense_b   = (const float*)d_in[7];
    const int*   src       = (const int*)d_in[8];
    const int*   dst       = (const int*)d_in[9];

    float* nf2 = (float*)d_out;
    float* ef2 = (float*)d_out + (size_t)NN * DD;

    cudaFuncSetAttribute(scatter_ef, cudaFuncAttributeMaxDynamicSharedMemorySize, SCAT_SMEM);
    cudaFuncSetAttribute(node_pass_a, cudaFuncAttributeMaxDynamicSharedMemorySize, SMEM_BYTES);
    cudaFuncSetAttribute(node_pass_b, cudaFuncAttributeMaxDynamicSharedMemorySize, SMEM_BYTES);
    cudaFuncSetAttribute(edge_out_gemm, cudaFuncAttributeMaxDynamicSharedMemorySize, SMEM_EO);

    const int NBLK = (NN + 127) / 128;

    zero_kernel<<<1024, 256>>>();
    prep_weights<<<64, 256>>>(W_node, W_edge, dense_W);
    scatter_ef<<<NE / 128, 256, SCAT_SMEM>>>(ef, dst);
    node_pass_a<<<NBLK, 512, SMEM_BYTES>>>(nf, node_bias, nf2);
    node_pass_b<<<NBLK, 512, SMEM_BYTES>>>();
    edge_out_gemm<<<NE / 64, 256, SMEM_EO>>>(ef, src, dst, dense_b,
                                             edge_bias, ef2);
}

// round 14
// speedup vs baseline: 1.0331x; 1.0238x over previous
#include <cuda_runtime.h>
#include <cuda_bf16.h>
#include <cstdint>

#define NN 50000
#define NE 800000
#define DD 128

// ---------------- scratch (device globals; referenced ONLY in device code,
// except cudaGetSymbolAddress for memset) ---------------------------------------
__device__ __align__(512) float g_s[(size_t)NN * DD];   // segment_sum(ef, dst)
__device__ float g_deg[NN];
__device__ float g_t2[(size_t)NN * DD];   // nf2 @ Wd2
__device__ float g_t3[(size_t)NN * DD];   // (S/deg)@M + 0.5 * t2
// bf16 hi/lo splits, B layout: B[n][k] = W[k][n]
__device__ __nv_bfloat16 g_Bn_h[DD * DD], g_Bn_l[DD * DD];     // W_node
__device__ __nv_bfloat16 g_Bd2_h[DD * DD], g_Bd2_l[DD * DD];   // dense_W[128:256]
__device__ __nv_bfloat16 g_Bm_h[DD * DD], g_Bm_l[DD * DD];     // M = We@Wd1

// ---------------- smem layout (32-bit words) ----------------------------------
#define WPAD 68
#define SA_H 0
#define SA_L (128 * WPAD)
#define SB_H (2 * 128 * WPAD)
#define SB_L (3 * 128 * WPAD)
#define SMEM_BYTES (4 * 128 * WPAD * 4)   // 139264
#define SCAT_SMEM 65536

// ---------------- helpers ------------------------------------------------------
__device__ __forceinline__ uint32_t smem_u32(const void* p) {
    uint32_t a;
    asm("{ .reg .u64 t; cvta.to.shared.u64 t, %1; cvt.u32.u64 %0, t; }" : "=r"(a) : "l"(p));
    return a;
}

__device__ __forceinline__ void split2(float x, float y, uint32_t& hi, uint32_t& lo) {
    __nv_bfloat162 h = __floats2bfloat162_rn(x, y);
    hi = *(uint32_t*)&h;
    float rx = x - __bfloat162float(__low2bfloat16(h));
    float ry = y - __bfloat162float(__high2bfloat16(h));
    __nv_bfloat162 l = __floats2bfloat162_rn(rx, ry);
    lo = *(uint32_t*)&l;
}

__device__ __forceinline__ void mma_bf16(float* d, const uint32_t* a,
                                         uint32_t b0, uint32_t b1) {
    asm volatile(
        "mma.sync.aligned.m16n8k16.row.col.f32.bf16.bf16.f32 "
        "{%0,%1,%2,%3}, {%4,%5,%6,%7}, {%8,%9}, {%0,%1,%2,%3};"
        : "+f"(d[0]), "+f"(d[1]), "+f"(d[2]), "+f"(d[3])
        : "r"(a[0]), "r"(a[1]), "r"(a[2]), "r"(a[3]), "r"(b0), "r"(b1));
}

// 512 threads fill the B tile pair
__device__ __forceinline__ void fillB(uint32_t* sm, const __nv_bfloat16* bh,
                                      const __nv_bfloat16* bl, int tid) {
#pragma unroll
    for (int i = 0; i < 16; i++) {
        int idx = tid + i * 512;
        int n = idx >> 6, w = idx & 63;
        sm[SB_H + n * WPAD + w] = *(const uint32_t*)(bh + (size_t)n * DD + 2 * w);
        sm[SB_L + n * WPAD + w] = *(const uint32_t*)(bl + (size_t)n * DD + 2 * w);
    }
}

// K=128 loop: warp computes 32 rows x 32 cols with 3-way bf16 split
__device__ __forceinline__ void kloop(const uint32_t* sm, int lane, int mbase,
                                      int nbase, float acc[2][4][4]) {
    const int g = lane >> 2, t = lane & 3;
#pragma unroll
    for (int ks = 0; ks < 8; ks++) {
        const int kw = ks * 8 + t;
        uint32_t ah[2][4], al[2][4];
#pragma unroll
        for (int mt = 0; mt < 2; mt++) {
            int r = mbase + mt * 16 + g;
            ah[mt][0] = sm[SA_H + r * WPAD + kw];
            ah[mt][1] = sm[SA_H + (r + 8) * WPAD + kw];
            ah[mt][2] = sm[SA_H + r * WPAD + kw + 4];
            ah[mt][3] = sm[SA_H + (r + 8) * WPAD + kw + 4];
            al[mt][0] = sm[SA_L + r * WPAD + kw];
            al[mt][1] = sm[SA_L + (r + 8) * WPAD + kw];
            al[mt][2] = sm[SA_L + r * WPAD + kw + 4];
            al[mt][3] = sm[SA_L + (r + 8) * WPAD + kw + 4];
        }
#pragma unroll
        for (int j = 0; j < 4; j++) {
            int n = nbase + j * 8 + g;
            uint32_t bh0 = sm[SB_H + n * WPAD + kw];
            uint32_t bh1 = sm[SB_H + n * WPAD + kw + 4];
            uint32_t bl0 = sm[SB_L + n * WPAD + kw];
            uint32_t bl1 = sm[SB_L + n * WPAD + kw + 4];
#pragma unroll
            for (int mt = 0; mt < 2; mt++) {
                mma_bf16(acc[mt][j], ah[mt], bh0, bh1);
                mma_bf16(acc[mt][j], ah[mt], bl0, bl1);
                mma_bf16(acc[mt][j], al[mt], bh0, bh1);
            }
        }
    }
}

__device__ __forceinline__ void zero_acc(float acc[2][4][4]) {
#pragma unroll
    for (int a = 0; a < 2; a++)
#pragma unroll
        for (int b = 0; b < 4; b++)
#pragma unroll
            for (int c = 0; c < 4; c++) acc[a][b][c] = 0.f;
}

// write warp's acc patch back into the smem A tile (bf16 hi/lo re-split)
__device__ __forceinline__ void acc_to_sa(uint32_t* sm, const float acc[2][4][4],
                                          int mbase, int nbase, int lane) {
    const int g = lane >> 2, t = lane & 3;
#pragma unroll
    for (int mt = 0; mt < 2; mt++) {
        int rA = mbase + mt * 16 + g, rB = rA + 8;
#pragma unroll
        for (int j = 0; j < 4; j++) {
            int w = (nbase >> 1) + j * 4 + t;
            uint32_t hi, lo;
            split2(acc[mt][j][0], acc[mt][j][1], hi, lo);
            sm[SA_H + rA * WPAD + w] = hi;
            sm[SA_L + rA * WPAD + w] = lo;
            split2(acc[mt][j][2], acc[mt][j][3], hi, lo);
            sm[SA_H + rB * WPAD + w] = hi;
            sm[SA_L + rB * WPAD + w] = lo;
        }
    }
}

// ---------------- prep kernels --------------------------------------------------
// one kernel: splits of W_node, dense_W[128:], and M=We@Wd1 (dot inline)
__global__ void prep_weights(const float* __restrict__ Wn,
                             const float* __restrict__ We,
                             const float* __restrict__ dW) {
    int idx = blockIdx.x * blockDim.x + threadIdx.x;
    if (idx >= DD * DD) return;
    int n = idx >> 7, k = idx & 127;

    float v = Wn[(size_t)k * DD + n];
    __nv_bfloat16 h = __float2bfloat16(v);
    g_Bn_h[idx] = h;
    g_Bn_l[idx] = __float2bfloat16(v - __bfloat162float(h));

    v = dW[(size_t)(128 + k) * DD + n];
    h = __float2bfloat16(v);
    g_Bd2_h[idx] = h;
    g_Bd2_l[idx] = __float2bfloat16(v - __bfloat162float(h));

    float m = 0.f;
#pragma unroll 4
    for (int j = 0; j < DD; j++)
        m = fmaf(We[(size_t)k * DD + j], dW[(size_t)j * DD + n], m);
    h = __float2bfloat16(m);
    g_Bm_h[idx] = h;
    g_Bm_l[idx] = __float2bfloat16(m - __bfloat162float(h));
}

// scatter 128 contiguous ef rows via smem + TMA bulk reductions
__global__ __launch_bounds__(256)
void scatter_ef(const float* __restrict__ ef, const int* __restrict__ dst) {
    extern __shared__ __align__(16) float buf[];   // 128 rows x 128 f32 = 64KB
    const int tid = threadIdx.x;
    const int e0 = blockIdx.x * 128;
    const float4* src = (const float4*)(ef + (size_t)e0 * DD);
    float4* b4 = (float4*)buf;
#pragma unroll
    for (int i = 0; i < 16; i++)
        b4[tid + i * 256] = src[tid + i * 256];
    __syncthreads();
    asm volatile("fence.proxy.async.shared::cta;" ::: "memory");
    if (tid < 128) {
        int e = e0 + tid;
        int dn = dst[e];
        uint32_t sptr = smem_u32(buf + tid * DD);
        float* gptr = g_s + (size_t)dn * DD;
        asm volatile(
            "cp.reduce.async.bulk.global.shared::cta.bulk_group.add.f32 [%0], [%1], 512;"
            :: "l"(gptr), "r"(sptr) : "memory");
        asm volatile("red.global.add.f32 [%0], %1;"
                     :: "l"(g_deg + dn), "f"(1.0f) : "memory");
    }
    asm volatile("cp.async.bulk.commit_group;" ::: "memory");
    asm volatile("cp.async.bulk.wait_group 0;" ::: "memory");
}

// ---------------- fused node pass A: nf2 = relu(nf@Wn + b); t2 = nf2@Wd2 -------
__global__ __launch_bounds__(512, 1)
void node_pass_a(const float* __restrict__ nf, const float* __restrict__ bias,
                 float* __restrict__ nf2out) {
    extern __shared__ uint32_t sm[];
    const int tid = threadIdx.x, lane = tid & 31, wid = tid >> 5;
    const int rowbase = blockIdx.x * 128;
    const int mbase = (wid & 3) * 32, nbase = (wid >> 2) * 32;
    const int g = lane >> 2, t = lane & 3;

    fillB(sm, g_Bn_h, g_Bn_l, tid);
#pragma unroll
    for (int i = 0; i < 16; i++) {
        int idx = tid + i * 512;
        int r = idx >> 6, w = idx & 63;
        int row = rowbase + r;
        float2 v = make_float2(0.f, 0.f);
        if (row < NN) v = *(const float2*)(nf + (size_t)row * DD + 2 * w);
        split2(v.x, v.y, sm[SA_H + r * WPAD + w], sm[SA_L + r * WPAD + w]);
    }
    __syncthreads();

    float acc[2][4][4];
    zero_acc(acc);
    kloop(sm, lane, mbase, nbase, acc);
    __syncthreads();

    // epilogue 1: bias + relu -> nf2 (global) and re-split into SA
#pragma unroll
    for (int mt = 0; mt < 2; mt++) {
        int rowA = rowbase + mbase + mt * 16 + g;
#pragma unroll
        for (int j = 0; j < 4; j++) {
            int c = nbase + j * 8 + 2 * t;
            float2 bv = *(const float2*)(bias + c);
            acc[mt][j][0] = fmaxf(acc[mt][j][0] + bv.x, 0.f);
            acc[mt][j][1] = fmaxf(acc[mt][j][1] + bv.y, 0.f);
            acc[mt][j][2] = fmaxf(acc[mt][j][2] + bv.x, 0.f);
            acc[mt][j][3] = fmaxf(acc[mt][j][3] + bv.y, 0.f);
            if (rowA < NN)
                *(float2*)(nf2out + (size_t)rowA * DD + c) =
                    make_float2(acc[mt][j][0], acc[mt][j][1]);
            if (rowA + 8 < NN)
                *(float2*)(nf2out + (size_t)(rowA + 8) * DD + c) =
                    make_float2(acc[mt][j][2], acc[mt][j][3]);
        }
    }
    acc_to_sa(sm, acc, mbase, nbase, lane);
    fillB(sm, g_Bd2_h, g_Bd2_l, tid);
    __syncthreads();

    zero_acc(acc);
    kloop(sm, lane, mbase, nbase, acc);

#pragma unroll
    for (int mt = 0; mt < 2; mt++) {
        int rowA = rowbase + mbase + mt * 16 + g;
#pragma unroll
        for (int j = 0; j < 4; j++) {
            int c = nbase + j * 8 + 2 * t;
            if (rowA < NN)
                *(float2*)(g_t2 + (size_t)rowA * DD + c) =
                    make_float2(acc[mt][j][0], acc[mt][j][1]);
            if (rowA + 8 < NN)
                *(float2*)(g_t2 + (size_t)(rowA + 8) * DD + c) =
                    make_float2(acc[mt][j][2], acc[mt][j][3]);
        }
    }
}

// ---------------- node pass B: t3 = (S/deg) @ M + 0.5*t2 ------------------------
__global__ __launch_bounds__(512, 1)
void node_pass_b() {
    extern __shared__ uint32_t sm[];
    const int tid = threadIdx.x, lane = tid & 31, wid = tid >> 5;
    const int rowbase = blockIdx.x * 128;
    const int mbase = (wid & 3) * 32, nbase = (wid >> 2) * 32;
    const int g = lane >> 2, t = lane & 3;

    fillB(sm, g_Bm_h, g_Bm_l, tid);
#pragma unroll
    for (int i = 0; i < 16; i++) {
        int idx = tid + i * 512;
        int r = idx >> 6, w = idx & 63;
        int row = rowbase + r;
        float2 v = make_float2(0.f, 0.f);
        if (row < NN) {
            float s = 1.f / fmaxf(g_deg[row], 1.f);
            v = *(const float2*)(g_s + (size_t)row * DD + 2 * w);
            v.x *= s; v.y *= s;
        }
        split2(v.x, v.y, sm[SA_H + r * WPAD + w], sm[SA_L + r * WPAD + w]);
    }
    __syncthreads();

    float acc[2][4][4];
    zero_acc(acc);
    kloop(sm, lane, mbase, nbase, acc);

#pragma unroll
    for (int mt = 0; mt < 2; mt++) {
        int rowA = rowbase + mbase + mt * 16 + g;
#pragma unroll
        for (int j = 0; j < 4; j++) {
            int c = nbase + j * 8 + 2 * t;
            if (rowA < NN) {
                float2 u = *(const float2*)(g_t2 + (size_t)rowA * DD + c);
                *(float2*)(g_t3 + (size_t)rowA * DD + c) =
                    make_float2(acc[mt][j][0] + 0.5f * u.x,
                                acc[mt][j][1] + 0.5f * u.y);
            }
            if (rowA + 8 < NN) {
                float2 u = *(const float2*)(g_t2 + (size_t)(rowA + 8) * DD + c);
                *(float2*)(g_t3 + (size_t)(rowA + 8) * DD + c) =
                    make_float2(acc[mt][j][2] + 0.5f * u.x,
                                acc[mt][j][3] + 0.5f * u.y);
            }
        }
    }
}

// ---------------- fused edge output kernel (R11 config) -------------------------
// ef2 = relu(ef @ M + t3[dst] + 0.5*t2[src] + db + eb)
__global__ __launch_bounds__(512, 1)
void edge_out_gemm(const float* __restrict__ ef, const int* __restrict__ src,
                   const int* __restrict__ dst, const float* __restrict__ db,
                   const float* __restrict__ eb, float* __restrict__ out) {
    extern __shared__ uint32_t sm[];
    const int tid = threadIdx.x, lane = tid & 31, wid = tid >> 5;
    const int e0 = blockIdx.x * 128;
    const int mbase = (wid & 3) * 32, nbase = (wid >> 2) * 32;
    const int g = lane >> 2, t = lane & 3;

    fillB(sm, g_Bm_h, g_Bm_l, tid);
#pragma unroll
    for (int i = 0; i < 16; i++) {
        int idx = tid + i * 512;
        int r = idx >> 6, w = idx & 63;
        float2 v = *(const float2*)(ef + (size_t)(e0 + r) * DD + 2 * w);
        split2(v.x, v.y, sm[SA_H + r * WPAD + w], sm[SA_L + r * WPAD + w]);
    }
    __syncthreads();

    float acc[2][4][4];
    zero_acc(acc);
    kloop(sm, lane, mbase, nbase, acc);

#pragma unroll
    for (int mt = 0; mt < 2; mt++) {
        int e = e0 + mbase + mt * 16 + g;
        int dnA = dst[e], snA = src[e];
        int dnB = dst[e + 8], snB = src[e + 8];
        const float* t3A = g_t3 + (size_t)dnA * DD;
        const float* t2A = g_t2 + (size_t)snA * DD;
        const float* t3B = g_t3 + (size_t)dnB * DD;
        const float* t2B = g_t2 + (size_t)snB * DD;
#pragma unroll
        for (int j = 0; j < 4; j++) {
            int c = nbase + j * 8 + 2 * t;
            float2 d1 = *(const float2*)(db + c);
            float2 d2 = *(const float2*)(eb + c);
            float bx = d1.x + d2.x, by = d1.y + d2.y;

            float2 p1 = *(const float2*)(t3A + c);
            float2 p2 = *(const float2*)(t2A + c);
            float2 oA;
            oA.x = fmaxf(acc[mt][j][0] + p1.x + 0.5f * p2.x + bx, 0.f);
            oA.y = fmaxf(acc[mt][j][1] + p1.y + 0.5f * p2.y + by, 0.f);
            *(float2*)(out + (size_t)e * DD + c) = oA;

            float2 q1 = *(const float2*)(t3B + c);
            float2 q2 = *(const float2*)(t2B + c);
            float2 oB;
            oB.x = fmaxf(acc[mt][j][2] + q1.x + 0.5f * q2.x + bx, 0.f);
            oB.y = fmaxf(acc[mt][j][3] + q1.y + 0.5f * q2.y + by, 0.f);
            *(float2*)(out + (size_t)(e + 8) * DD + c) = oB;
        }
    }
}

// ---------------- launch ------------------------------------------------------
extern "C" void kernel_launch(void* const* d_in, const int* in_sizes, int n_in,
                              void* d_out, int out_size) {
    (void)in_sizes; (void)n_in; (void)out_size;
    const float* nf        = (const float*)d_in[0];
    const float* ef        = (const float*)d_in[1];
    const float* W_node    = (const float*)d_in[2];
    const float* W_edge    = (const float*)d_in[3];
    const float* node_bias = (const float*)d_in[4];
    const float* edge_bias = (const float*)d_in[5];
    const float* dense_W   = (const float*)d_in[6];
    const float* dense_b   = (const float*)d_in[7];
    const int*   src       = (const int*)d_in[8];
    const int*   dst       = (const int*)d_in[9];

    float* nf2 = (float*)d_out;
    float* ef2 = (float*)d_out + (size_t)NN * DD;

    // one-time setup (first call happens OUTSIDE graph capture)
    static cudaStream_t s2 = nullptr;
    static cudaEvent_t evFork = nullptr, evJoin = nullptr;
    static void *p_s = nullptr, *p_deg = nullptr;
    if (!s2) {
        cudaStreamCreateWithFlags(&s2, cudaStreamNonBlocking);
        cudaEventCreateWithFlags(&evFork, cudaEventDisableTiming);
        cudaEventCreateWithFlags(&evJoin, cudaEventDisableTiming);
        cudaGetSymbolAddress(&p_s, g_s);
        cudaGetSymbolAddress(&p_deg, g_deg);
    }

    cudaFuncSetAttribute(scatter_ef, cudaFuncAttributeMaxDynamicSharedMemorySize, SCAT_SMEM);
    cudaFuncSetAttribute(node_pass_a, cudaFuncAttributeMaxDynamicSharedMemorySize, SMEM_BYTES);
    cudaFuncSetAttribute(node_pass_b, cudaFuncAttributeMaxDynamicSharedMemorySize, SMEM_BYTES);
    cudaFuncSetAttribute(edge_out_gemm, cudaFuncAttributeMaxDynamicSharedMemorySize, SMEM_BYTES);

    const int NBLK = (NN + 127) / 128;

    // fork: s2 runs [memset g_s,g_deg -> scatter]; main runs [prep -> pass_a]
    cudaEventRecord(evFork, 0);
    cudaStreamWaitEvent(s2, evFork, 0);
    cudaMemsetAsync(p_s, 0, (size_t)NN * DD * sizeof(float), s2);
    cudaMemsetAsync(p_deg, 0, (size_t)NN * sizeof(float), s2);
    scatter_ef<<<NE / 128, 256, SCAT_SMEM, s2>>>(ef, dst);
    cudaEventRecord(evJoin, s2);

    prep_weights<<<64, 256>>>(W_node, W_edge, dense_W);
    node_pass_a<<<NBLK, 512, SMEM_BYTES>>>(nf, node_bias, nf2);

    cudaStreamWaitEvent(0, evJoin, 0);   // join: pass_b needs g_s/g_deg
    node_pass_b<<<NBLK, 512, SMEM_BYTES>>>();
    edge_out_gemm<<<NE / 128, 512, SMEM_BYTES>>>(ef, src, dst, dense_b,
                                                 edge_bias, ef2);
}

// round 17
// speedup vs baseline: 1.1054x; 1.0700x over previous
#include <cuda_runtime.h>
#include <cuda_bf16.h>
#include <cstdint>

#define NN 50000
#define NE 800000
#define DD 128

// ---------------- scratch (device globals; referenced ONLY in device code,
// except cudaGetSymbolAddress for memset) ---------------------------------------
__device__ __align__(512) float g_s[(size_t)NN * DD];   // segment_sum(ef, dst)
__device__ float g_deg[NN];
__device__ float g_t2[(size_t)NN * DD];   // nf2 @ Wd2
__device__ float g_t3[(size_t)NN * DD];   // (S/deg)@M + 0.5 * t2
// bf16 hi/lo splits, B layout: B[n][k] = W[k][n]
__device__ __nv_bfloat16 g_Bn_h[DD * DD], g_Bn_l[DD * DD];     // W_node
__device__ __nv_bfloat16 g_Bd2_h[DD * DD], g_Bd2_l[DD * DD];   // dense_W[128:256]
__device__ __nv_bfloat16 g_Bm_h[DD * DD], g_Bm_l[DD * DD];     // M = We@Wd1

// ---------------- smem layout (32-bit words) ----------------------------------
#define WPAD 68
#define SA_H 0
#define SA_L (128 * WPAD)
#define SB_H (2 * 128 * WPAD)
#define SB_L (3 * 128 * WPAD)
#define SMEM_BYTES (4 * 128 * WPAD * 4)   // 139264
#define SCAT_SMEM 65536

// ---------------- cache-hinted accessors (.cs = streaming, evict-first) ---------
__device__ __forceinline__ float2 ld_cs2(const float* p) {
    float2 v;
    asm volatile("ld.global.cs.v2.f32 {%0,%1}, [%2];"
                 : "=f"(v.x), "=f"(v.y) : "l"(p));
    return v;
}
__device__ __forceinline__ float4 ld_cs4(const float* p) {
    float4 v;
    asm volatile("ld.global.cs.v4.f32 {%0,%1,%2,%3}, [%4];"
                 : "=f"(v.x), "=f"(v.y), "=f"(v.z), "=f"(v.w) : "l"(p));
    return v;
}
__device__ __forceinline__ void st_cs2(float* p, float2 v) {
    asm volatile("st.global.cs.v2.f32 [%0], {%1,%2};"
                 :: "l"(p), "f"(v.x), "f"(v.y) : "memory");
}

// ---------------- helpers ------------------------------------------------------
__device__ __forceinline__ uint32_t smem_u32(const void* p) {
    uint32_t a;
    asm("{ .reg .u64 t; cvta.to.shared.u64 t, %1; cvt.u32.u64 %0, t; }" : "=r"(a) : "l"(p));
    return a;
}

__device__ __forceinline__ void split2(float x, float y, uint32_t& hi, uint32_t& lo) {
    __nv_bfloat162 h = __floats2bfloat162_rn(x, y);
    hi = *(uint32_t*)&h;
    float rx = x - __bfloat162float(__low2bfloat16(h));
    float ry = y - __bfloat162float(__high2bfloat16(h));
    __nv_bfloat162 l = __floats2bfloat162_rn(rx, ry);
    lo = *(uint32_t*)&l;
}

__device__ __forceinline__ void mma_bf16(float* d, const uint32_t* a,
                                         uint32_t b0, uint32_t b1) {
    asm volatile(
        "mma.sync.aligned.m16n8k16.row.col.f32.bf16.bf16.f32 "
        "{%0,%1,%2,%3}, {%4,%5,%6,%7}, {%8,%9}, {%0,%1,%2,%3};"
        : "+f"(d[0]), "+f"(d[1]), "+f"(d[2]), "+f"(d[3])
        : "r"(a[0]), "r"(a[1]), "r"(a[2]), "r"(a[3]), "r"(b0), "r"(b1));
}

// 512 threads fill the B tile pair
__device__ __forceinline__ void fillB(uint32_t* sm, const __nv_bfloat16* bh,
                                      const __nv_bfloat16* bl, int tid) {
#pragma unroll
    for (int i = 0; i < 16; i++) {
        int idx = tid + i * 512;
        int n = idx >> 6, w = idx & 63;
        sm[SB_H + n * WPAD + w] = *(const uint32_t*)(bh + (size_t)n * DD + 2 * w);
        sm[SB_L + n * WPAD + w] = *(const uint32_t*)(bl + (size_t)n * DD + 2 * w);
    }
}

// K=128 loop: warp computes 32 rows x 32 cols with 3-way bf16 split
__device__ __forceinline__ void kloop(const uint32_t* sm, int lane, int mbase,
                                      int nbase, float acc[2][4][4]) {
    const int g = lane >> 2, t = lane & 3;
#pragma unroll
    for (int ks = 0; ks < 8; ks++) {
        const int kw = ks * 8 + t;
        uint32_t ah[2][4], al[2][4];
#pragma unroll
        for (int mt = 0; mt < 2; mt++) {
            int r = mbase + mt * 16 + g;
            ah[mt][0] = sm[SA_H + r * WPAD + kw];
            ah[mt][1] = sm[SA_H + (r + 8) * WPAD + kw];
            ah[mt][2] = sm[SA_H + r * WPAD + kw + 4];
            ah[mt][3] = sm[SA_H + (r + 8) * WPAD + kw + 4];
            al[mt][0] = sm[SA_L + r * WPAD + kw];
            al[mt][1] = sm[SA_L + (r + 8) * WPAD + kw];
            al[mt][2] = sm[SA_L + r * WPAD + kw + 4];
            al[mt][3] = sm[SA_L + (r + 8) * WPAD + kw + 4];
        }
#pragma unroll
        for (int j = 0; j < 4; j++) {
            int n = nbase + j * 8 + g;
            uint32_t bh0 = sm[SB_H + n * WPAD + kw];
            uint32_t bh1 = sm[SB_H + n * WPAD + kw + 4];
            uint32_t bl0 = sm[SB_L + n * WPAD + kw];
            uint32_t bl1 = sm[SB_L + n * WPAD + kw + 4];
#pragma unroll
            for (int mt = 0; mt < 2; mt++) {
                mma_bf16(acc[mt][j], ah[mt], bh0, bh1);
                mma_bf16(acc[mt][j], ah[mt], bl0, bl1);
                mma_bf16(acc[mt][j], al[mt], bh0, bh1);
            }
        }
    }
}

__device__ __forceinline__ void zero_acc(float acc[2][4][4]) {
#pragma unroll
    for (int a = 0; a < 2; a++)
#pragma unroll
        for (int b = 0; b < 4; b++)
#pragma unroll
            for (int c = 0; c < 4; c++) acc[a][b][c] = 0.f;
}

// write warp's acc patch back into the smem A tile (bf16 hi/lo re-split)
__device__ __forceinline__ void acc_to_sa(uint32_t* sm, const float acc[2][4][4],
                                          int mbase, int nbase, int lane) {
    const int g = lane >> 2, t = lane & 3;
#pragma unroll
    for (int mt = 0; mt < 2; mt++) {
        int rA = mbase + mt * 16 + g, rB = rA + 8;
#pragma unroll
        for (int j = 0; j < 4; j++) {
            int w = (nbase >> 1) + j * 4 + t;
            uint32_t hi, lo;
            split2(acc[mt][j][0], acc[mt][j][1], hi, lo);
            sm[SA_H + rA * WPAD + w] = hi;
            sm[SA_L + rA * WPAD + w] = lo;
            split2(acc[mt][j][2], acc[mt][j][3], hi, lo);
            sm[SA_H + rB * WPAD + w] = hi;
            sm[SA_L + rB * WPAD + w] = lo;
        }
    }
}

// ---------------- prep kernels --------------------------------------------------
// one kernel: splits of W_node, dense_W[128:], and M=We@Wd1 (dot inline)
__global__ void prep_weights(const float* __restrict__ Wn,
                             const float* __restrict__ We,
                             const float* __restrict__ dW) {
    int idx = blockIdx.x * blockDim.x + threadIdx.x;
    if (idx >= DD * DD) return;
    int n = idx >> 7, k = idx & 127;

    float v = Wn[(size_t)k * DD + n];
    __nv_bfloat16 h = __float2bfloat16(v);
    g_Bn_h[idx] = h;
    g_Bn_l[idx] = __float2bfloat16(v - __bfloat162float(h));

    v = dW[(size_t)(128 + k) * DD + n];
    h = __float2bfloat16(v);
    g_Bd2_h[idx] = h;
    g_Bd2_l[idx] = __float2bfloat16(v - __bfloat162float(h));

    float m = 0.f;
#pragma unroll 4
    for (int j = 0; j < DD; j++)
        m = fmaf(We[(size_t)k * DD + j], dW[(size_t)j * DD + n], m);
    h = __float2bfloat16(m);
    g_Bm_h[idx] = h;
    g_Bm_l[idx] = __float2bfloat16(m - __bfloat162float(h));
}

// scatter 128 contiguous ef rows via smem + TMA bulk reductions
__global__ __launch_bounds__(256)
void scatter_ef(const float* __restrict__ ef, const int* __restrict__ dst) {
    extern __shared__ __align__(16) float buf[];   // 128 rows x 128 f32 = 64KB
    const int tid = threadIdx.x;
    const int e0 = blockIdx.x * 128;
    const float* src = ef + (size_t)e0 * DD;
    float4* b4 = (float4*)buf;
#pragma unroll
    for (int i = 0; i < 16; i++)
        b4[tid + i * 256] = ld_cs4(src + (tid + i * 256) * 4);
    __syncthreads();
    asm volatile("fence.proxy.async.shared::cta;" ::: "memory");
    if (tid < 128) {
        int e = e0 + tid;
        int dn = dst[e];
        uint32_t sptr = smem_u32(buf + tid * DD);
        float* gptr = g_s + (size_t)dn * DD;
        asm volatile(
            "cp.reduce.async.bulk.global.shared::cta.bulk_group.add.f32 [%0], [%1], 512;"
            :: "l"(gptr), "r"(sptr) : "memory");
        asm volatile("red.global.add.f32 [%0], %1;"
                     :: "l"(g_deg + dn), "f"(1.0f) : "memory");
    }
    asm volatile("cp.async.bulk.commit_group;" ::: "memory");
    asm volatile("cp.async.bulk.wait_group 0;" ::: "memory");
}

// ---------------- fused node pass A: nf2 = relu(nf@Wn + b); t2 = nf2@Wd2 -------
__global__ __launch_bounds__(512, 1)
void node_pass_a(const float* __restrict__ nf, const float* __restrict__ bias,
                 float* __restrict__ nf2out) {
    extern __shared__ uint32_t sm[];
    const int tid = threadIdx.x, lane = tid & 31, wid = tid >> 5;
    const int rowbase = blockIdx.x * 128;
    const int mbase = (wid & 3) * 32, nbase = (wid >> 2) * 32;
    const int g = lane >> 2, t = lane & 3;

    fillB(sm, g_Bn_h, g_Bn_l, tid);
#pragma unroll
    for (int i = 0; i < 16; i++) {
        int idx = tid + i * 512;
        int r = idx >> 6, w = idx & 63;
        int row = rowbase + r;
        float2 v = make_float2(0.f, 0.f);
        if (row < NN) v = ld_cs2(nf + (size_t)row * DD + 2 * w);
        split2(v.x, v.y, sm[SA_H + r * WPAD + w], sm[SA_L + r * WPAD + w]);
    }
    __syncthreads();

    float acc[2][4][4];
    zero_acc(acc);
    kloop(sm, lane, mbase, nbase, acc);
    __syncthreads();

    // epilogue 1: bias + relu -> nf2 (global, write-streaming) and re-split into SA
#pragma unroll
    for (int mt = 0; mt < 2; mt++) {
        int rowA = rowbase + mbase + mt * 16 + g;
#pragma unroll
        for (int j = 0; j < 4; j++) {
            int c = nbase + j * 8 + 2 * t;
            float2 bv = *(const float2*)(bias + c);
            acc[mt][j][0] = fmaxf(acc[mt][j][0] + bv.x, 0.f);
            acc[mt][j][1] = fmaxf(acc[mt][j][1] + bv.y, 0.f);
            acc[mt][j][2] = fmaxf(acc[mt][j][2] + bv.x, 0.f);
            acc[mt][j][3] = fmaxf(acc[mt][j][3] + bv.y, 0.f);
            if (rowA < NN)
                st_cs2(nf2out + (size_t)rowA * DD + c,
                       make_float2(acc[mt][j][0], acc[mt][j][1]));
            if (rowA + 8 < NN)
                st_cs2(nf2out + (size_t)(rowA + 8) * DD + c,
                       make_float2(acc[mt][j][2], acc[mt][j][3]));
        }
    }
    acc_to_sa(sm, acc, mbase, nbase, lane);
    fillB(sm, g_Bd2_h, g_Bd2_l, tid);
    __syncthreads();

    zero_acc(acc);
    kloop(sm, lane, mbase, nbase, acc);

#pragma unroll
    for (int mt = 0; mt < 2; mt++) {
        int rowA = rowbase + mbase + mt * 16 + g;
#pragma unroll
        for (int j = 0; j < 4; j++) {
            int c = nbase + j * 8 + 2 * t;
            if (rowA < NN)
                *(float2*)(g_t2 + (size_t)rowA * DD + c) =
                    make_float2(acc[mt][j][0], acc[mt][j][1]);
            if (rowA + 8 < NN)
                *(float2*)(g_t2 + (size_t)(rowA + 8) * DD + c) =
                    make_float2(acc[mt][j][2], acc[mt][j][3]);
        }
    }
}

// ---------------- node pass B: t3 = (S/deg) @ M + 0.5*t2 ------------------------
__global__ __launch_bounds__(512, 1)
void node_pass_b() {
    extern __shared__ uint32_t sm[];
    const int tid = threadIdx.x, lane = tid & 31, wid = tid >> 5;
    const int rowbase = blockIdx.x * 128;
    const int mbase = (wid & 3) * 32, nbase = (wid >> 2) * 32;
    const int g = lane >> 2, t = lane & 3;

    fillB(sm, g_Bm_h, g_Bm_l, tid);
#pragma unroll
    for (int i = 0; i < 16; i++) {
        int idx = tid + i * 512;
        int r = idx >> 6, w = idx & 63;
        int row = rowbase + r;
        float2 v = make_float2(0.f, 0.f);
        if (row < NN) {
            float s = 1.f / fmaxf(g_deg[row], 1.f);
            v = ld_cs2(g_s + (size_t)row * DD + 2 * w);
            v.x *= s; v.y *= s;
        }
        split2(v.x, v.y, sm[SA_H + r * WPAD + w], sm[SA_L + r * WPAD + w]);
    }
    __syncthreads();

    float acc[2][4][4];
    zero_acc(acc);
    kloop(sm, lane, mbase, nbase, acc);

#pragma unroll
    for (int mt = 0; mt < 2; mt++) {
        int rowA = rowbase + mbase + mt * 16 + g;
#pragma unroll
        for (int j = 0; j < 4; j++) {
            int c = nbase + j * 8 + 2 * t;
            if (rowA < NN) {
                float2 u = *(const float2*)(g_t2 + (size_t)rowA * DD + c);
                *(float2*)(g_t3 + (size_t)rowA * DD + c) =
                    make_float2(acc[mt][j][0] + 0.5f * u.x,
                                acc[mt][j][1] + 0.5f * u.y);
            }
            if (rowA + 8 < NN) {
                float2 u = *(const float2*)(g_t2 + (size_t)(rowA + 8) * DD + c);
                *(float2*)(g_t3 + (size_t)(rowA + 8) * DD + c) =
                    make_float2(acc[mt][j][2] + 0.5f * u.x,
                                acc[mt][j][3] + 0.5f * u.y);
            }
        }
    }
}

// ---------------- fused edge output kernel (R11 config + cache hints) -----------
// ef2 = relu(ef @ M + t3[dst] + 0.5*t2[src] + db + eb)
__global__ __launch_bounds__(512, 1)
void edge_out_gemm(const float* __restrict__ ef, const int* __restrict__ src,
                   const int* __restrict__ dst, const float* __restrict__ db,
                   const float* __restrict__ eb, float* __restrict__ out) {
    extern __shared__ uint32_t sm[];
    const int tid = threadIdx.x, lane = tid & 31, wid = tid >> 5;
    const int e0 = blockIdx.x * 128;
    const int mbase = (wid & 3) * 32, nbase = (wid >> 2) * 32;
    const int g = lane >> 2, t = lane & 3;

    fillB(sm, g_Bm_h, g_Bm_l, tid);
#pragma unroll
    for (int i = 0; i < 16; i++) {
        int idx = tid + i * 512;
        int r = idx >> 6, w = idx & 63;
        float2 v = ld_cs2(ef + (size_t)(e0 + r) * DD + 2 * w);
        split2(v.x, v.y, sm[SA_H + r * WPAD + w], sm[SA_L + r * WPAD + w]);
    }
    __syncthreads();

    float acc[2][4][4];
    zero_acc(acc);
    kloop(sm, lane, mbase, nbase, acc);

#pragma unroll
    for (int mt = 0; mt < 2; mt++) {
        int e = e0 + mbase + mt * 16 + g;
        int dnA = dst[e], snA = src[e];
        int dnB = dst[e + 8], snB = src[e + 8];
        const float* t3A = g_t3 + (size_t)dnA * DD;
        const float* t2A = g_t2 + (size_t)snA * DD;
        const float* t3B = g_t3 + (size_t)dnB * DD;
        const float* t2B = g_t2 + (size_t)snB * DD;
#pragma unroll
        for (int j = 0; j < 4; j++) {
            int c = nbase + j * 8 + 2 * t;
            float2 d1 = *(const float2*)(db + c);
            float2 d2 = *(const float2*)(eb + c);
            float bx = d1.x + d2.x, by = d1.y + d2.y;

            float2 p1 = *(const float2*)(t3A + c);
            float2 p2 = *(const float2*)(t2A + c);
            float2 oA;
            oA.x = fmaxf(acc[mt][j][0] + p1.x + 0.5f * p2.x + bx, 0.f);
            oA.y = fmaxf(acc[mt][j][1] + p1.y + 0.5f * p2.y + by, 0.f);
            st_cs2(out + (size_t)e * DD + c, oA);

            float2 q1 = *(const float2*)(t3B + c);
            float2 q2 = *(const float2*)(t2B + c);
            float2 oB;
            oB.x = fmaxf(acc[mt][j][2] + q1.x + 0.5f * q2.x + bx, 0.f);
            oB.y = fmaxf(acc[mt][j][3] + q1.y + 0.5f * q2.y + by, 0.f);
            st_cs2(out + (size_t)(e + 8) * DD + c, oB);
        }
    }
}

// ---------------- launch ------------------------------------------------------
extern "C" void kernel_launch(void* const* d_in, const int* in_sizes, int n_in,
                              void* d_out, int out_size) {
    (void)in_sizes; (void)n_in; (void)out_size;
    const float* nf        = (const float*)d_in[0];
    const float* ef        = (const float*)d_in[1];
    const float* W_node    = (const float*)d_in[2];
    const float* W_edge    = (const float*)d_in[3];
    const float* node_bias = (const float*)d_in[4];
    const float* edge_bias = (const float*)d_in[5];
    const float* dense_W   = (const float*)d_in[6];
    const float* dense_b   = (const float*)d_in[7];
    const int*   src       = (const int*)d_in[8];
    const int*   dst       = (const int*)d_in[9];

    float* nf2 = (float*)d_out;
    float* ef2 = (float*)d_out + (size_t)NN * DD;

    // one-time setup (first call happens OUTSIDE graph capture)
    static void *p_s = nullptr, *p_deg = nullptr;
    if (!p_s) {
        cudaGetSymbolAddress(&p_s, g_s);
        cudaGetSymbolAddress(&p_deg, g_deg);
    }

    cudaFuncSetAttribute(scatter_ef, cudaFuncAttributeMaxDynamicSharedMemorySize, SCAT_SMEM);
    cudaFuncSetAttribute(node_pass_a, cudaFuncAttributeMaxDynamicSharedMemorySize, SMEM_BYTES);
    cudaFuncSetAttribute(node_pass_b, cudaFuncAttributeMaxDynamicSharedMemorySize, SMEM_BYTES);
    cudaFuncSetAttribute(edge_out_gemm, cudaFuncAttributeMaxDynamicSharedMemorySize, SMEM_BYTES);

    const int NBLK = (NN + 127) / 128;

    cudaMemsetAsync(p_s, 0, (size_t)NN * DD * sizeof(float), 0);
    cudaMemsetAsync(p_deg, 0, (size_t)NN * sizeof(float), 0);
    prep_weights<<<64, 256>>>(W_node, W_edge, dense_W);
    scatter_ef<<<NE / 128, 256, SCAT_SMEM>>>(ef, dst);
    node_pass_a<<<NBLK, 512, SMEM_BYTES>>>(nf, node_bias, nf2);
    node_pass_b<<<NBLK, 512, SMEM_BYTES>>>();
    edge_out_gemm<<<NE / 128, 512, SMEM_BYTES>>>(ef, src, dst, dense_b,
                                                 edge_bias, ef2);
}